// round 16
// baseline (speedup 1.0000x reference)
#include <cuda_runtime.h>
#include <cuda_bf16.h>
#include <cstdint>

// ---------------------------------------------------------------------------
// YOLOv3 heads via warp-level tensor-core MMA (mma.sync m16n8k16 bf16 -> HMMA
// on sm_103; tcgen05 is gated behind the sm_103a PTX target which this
// toolchain does not emit). Per batch b: P = W(255xK) * F(K x HW) + bias,
// fused YOLO decode epilogue.
//
// fp32 accuracy via bf16 split: x = hi + lo; D += Ahi*Bhi + Ahi*Blo + Alo*Bhi
// (dropped lo*lo term ~2^-18 relative).
//
// Block: 256 thr / 8 warps, tile M=128(channels) x N=128(spatial), K-chunk 64.
// Warp tile 64x32 = 4x4 (m16n8k16) fragments.
//
// R12 fix: F rows are only 16B-aligned when HW % 4 == 0 (head13 has HW=169),
// so the float4 F load is now gated on (HW & 3) == 0; otherwise 4 predicated
// scalar loads. W arrays are __align__(16) for the uint4 tile reads.
// ---------------------------------------------------------------------------

__device__ __forceinline__ uint32_t smem_u32(const void* p) {
    uint32_t a;
    asm("{ .reg .u64 t; cvta.to.shared.u64 t, %1; cvt.u32.u64 %0, t; }"
        : "=r"(a) : "l"(p));
    return a;
}
__device__ __forceinline__ void ldmx4(uint32_t* r, uint32_t addr) {
    asm volatile("ldmatrix.sync.aligned.m8n8.x4.shared.b16 {%0,%1,%2,%3}, [%4];"
                 : "=r"(r[0]), "=r"(r[1]), "=r"(r[2]), "=r"(r[3]) : "r"(addr));
}
__device__ __forceinline__ void ldmx4t(uint32_t* r, uint32_t addr) {
    asm volatile("ldmatrix.sync.aligned.m8n8.x4.trans.shared.b16 {%0,%1,%2,%3}, [%4];"
                 : "=r"(r[0]), "=r"(r[1]), "=r"(r[2]), "=r"(r[3]) : "r"(addr));
}
__device__ __forceinline__ void mma_bf16(float* d, const uint32_t* a,
                                         uint32_t b0, uint32_t b1) {
    asm volatile("mma.sync.aligned.m16n8k16.row.col.f32.bf16.bf16.f32 "
                 "{%0,%1,%2,%3}, {%4,%5,%6,%7}, {%8,%9}, {%0,%1,%2,%3};"
                 : "+f"(d[0]), "+f"(d[1]), "+f"(d[2]), "+f"(d[3])
                 : "r"(a[0]), "r"(a[1]), "r"(a[2]), "r"(a[3]), "r"(b0), "r"(b1));
}

// W split into bf16 hi/lo, padded to 256 rows (row >= 255 zero), [m][k] row-major
__device__ __align__(16) __nv_bfloat16 g_Whi13[256 * 1024];
__device__ __align__(16) __nv_bfloat16 g_Wlo13[256 * 1024];
__device__ __align__(16) __nv_bfloat16 g_Whi26[256 * 512];
__device__ __align__(16) __nv_bfloat16 g_Wlo26[256 * 512];
__device__ __align__(16) __nv_bfloat16 g_Whi52[256 * 256];
__device__ __align__(16) __nv_bfloat16 g_Wlo52[256 * 256];

__global__ void prep_kernel(const float* __restrict__ W13,
                            const float* __restrict__ W26,
                            const float* __restrict__ W52) {
    int idx = blockIdx.x * blockDim.x + threadIdx.x;
    if (idx < 256 * 1024) {
        int m = idx >> 10, k = idx & 1023;
        float w = (m < 255) ? W13[m * 1024 + k] : 0.f;
        __nv_bfloat16 hi = __float2bfloat16_rn(w);
        g_Whi13[idx] = hi;
        g_Wlo13[idx] = __float2bfloat16_rn(w - __bfloat162float(hi));
    }
    if (idx < 256 * 512) {
        int m = idx >> 9, k = idx & 511;
        float w = (m < 255) ? W26[m * 512 + k] : 0.f;
        __nv_bfloat16 hi = __float2bfloat16_rn(w);
        g_Whi26[idx] = hi;
        g_Wlo26[idx] = __float2bfloat16_rn(w - __bfloat162float(hi));
    }
    if (idx < 256 * 256) {
        int m = idx >> 8, k = idx & 255;
        float w = (m < 255) ? W52[m * 256 + k] : 0.f;
        __nv_bfloat16 hi = __float2bfloat16_rn(w);
        g_Whi52[idx] = hi;
        g_Wlo52[idx] = __float2bfloat16_rn(w - __bfloat162float(hi));
    }
}

__device__ __forceinline__ float sigmoidf_(float v) {
    return 1.f / (1.f + __expf(-v));
}

// SMEM layout (dynamic, bytes):
//   [0]      bias (128 f32) -> 512, pad to 1024
//   [1024]   sWhi [128][72] bf16 (rows padded 144B)   = 18432
//   [19456]  sWlo                                      = 18432
//   [37888]  sFhi [64][136] bf16 (rows padded 272B)    = 17408
//   [55296]  sFlo                                      = 17408   -> 72704
//   stage [128 spatial][134] f32 = 68608 reuses [1024, 69632)
static constexpr int SM_BIAS  = 0;
static constexpr int SM_WHI   = 1024;
static constexpr int SM_WLO   = 19456;
static constexpr int SM_FHI   = 37888;
static constexpr int SM_FLO   = 55296;
static constexpr int SM_STAGE = 1024;
static constexpr int SMEM_TOTAL = 72704;
static constexpr int WROW = 144;   // bytes per W smem row (64 bf16 + pad)
static constexpr int FROW = 272;   // bytes per F smem row (128 bf16 + pad)
static constexpr int STR  = 134;   // stage row stride (floats)

__global__ __launch_bounds__(256)
void head_mma(const float* __restrict__ F,
              int head,                       // 0:13  1:26  2:52
              const float* __restrict__ bias,
              float* __restrict__ out,
              int K, int S, int HW, float invS,
              float aw0, float ah0, float aw1, float ah1, float aw2, float ah2)
{
    extern __shared__ char smem[];
    const uint32_t sb  = smem_u32(smem);
    const int tid  = threadIdx.x;
    const int lane = tid & 31;
    const int wid  = tid >> 5;
    const int wm   = wid >> 2;           // 0..1  (64 channel rows)
    const int wn   = wid & 3;            // 0..3  (32 spatial cols)
    const int n0   = blockIdx.x * 128;   // spatial base
    const int m0   = blockIdx.y * 128;   // channel base
    const int b    = blockIdx.z;

    const __nv_bfloat16* __restrict__ Whi =
        (head == 0) ? g_Whi13 : (head == 1) ? g_Whi26 : g_Whi52;
    const __nv_bfloat16* __restrict__ Wlo =
        (head == 0) ? g_Wlo13 : (head == 1) ? g_Wlo26 : g_Wlo52;
    const float* __restrict__ Fb = F + (size_t)b * K * HW;
    const bool hw_vec4 = ((HW & 3) == 0);   // float4 path legal only then

    if (tid < 128) {
        int cg = m0 + tid;
        ((float*)(smem + SM_BIAS))[tid] = (cg < 255) ? bias[cg] : 0.f;
    }

    float acc[4][4][4];
#pragma unroll
    for (int i = 0; i < 4; i++)
#pragma unroll
        for (int j = 0; j < 4; j++)
#pragma unroll
            for (int r = 0; r < 4; r++) acc[i][j][r] = 0.f;

    for (int k0 = 0; k0 < K; k0 += 64) {
        __syncthreads();   // previous iteration's ldmatrix reads done
        // ---- W tiles: [128 rows][64 k] bf16 hi/lo, 16B chunks ----
#pragma unroll
        for (int i = 0; i < 4; i++) {
            int e = i * 256 + tid;        // 0..1023 uint4 slots (8 per row)
            int row = e >> 3, j = e & 7;
            size_t gidx = (((size_t)(m0 + row) * K + k0) >> 3) + j;
            uint32_t d = (uint32_t)(row * WROW + j * 16);
            *(uint4*)(smem + SM_WHI + d) = ((const uint4*)Whi)[gidx];
            *(uint4*)(smem + SM_WLO + d) = ((const uint4*)Wlo)[gidx];
        }
        // ---- F tiles: [64 k rows][128 n] fp32 -> bf16 hi/lo ----
#pragma unroll
        for (int i = 0; i < 8; i++) {
            int e   = i * 256 + tid;      // 0..2047 float4 slots (32 per row)
            int row = e >> 5, c4 = e & 31;
            int col = c4 * 4;
            int gc  = n0 + col;
            float v0, v1, v2, v3;
            const float* src = Fb + (size_t)(k0 + row) * HW + gc;
            if (hw_vec4 && gc + 3 < HW) {
                float4 f = *(const float4*)src;   // 16B-aligned: HW%4==0
                v0 = f.x; v1 = f.y; v2 = f.z; v3 = f.w;
            } else {
                v0 = (gc     < HW) ? src[0] : 0.f;
                v1 = (gc + 1 < HW) ? src[1] : 0.f;
                v2 = (gc + 2 < HW) ? src[2] : 0.f;
                v3 = (gc + 3 < HW) ? src[3] : 0.f;
            }
            __nv_bfloat16 h0 = __float2bfloat16_rn(v0), h1 = __float2bfloat16_rn(v1);
            __nv_bfloat16 h2 = __float2bfloat16_rn(v2), h3 = __float2bfloat16_rn(v3);
            __nv_bfloat162 hp0(h0, h1), hp1(h2, h3);
            __nv_bfloat162 lp0(__float2bfloat16_rn(v0 - __bfloat162float(h0)),
                               __float2bfloat16_rn(v1 - __bfloat162float(h1)));
            __nv_bfloat162 lp1(__float2bfloat16_rn(v2 - __bfloat162float(h2)),
                               __float2bfloat16_rn(v3 - __bfloat162float(h3)));
            uint32_t d = (uint32_t)(row * FROW + col * 2);
            *(uint2*)(smem + SM_FHI + d) =
                make_uint2(*(uint32_t*)&hp0, *(uint32_t*)&hp1);
            *(uint2*)(smem + SM_FLO + d) =
                make_uint2(*(uint32_t*)&lp0, *(uint32_t*)&lp1);
        }
        __syncthreads();

        // ---- 4 x k16 MMA steps ----
#pragma unroll
        for (int kk = 0; kk < 64; kk += 16) {
            uint32_t ahi[4][4], alo[4][4];
            uint32_t arow = (uint32_t)((wm * 64 + (lane & 15)) * WROW +
                                       (kk + (lane >> 4) * 8) * 2);
#pragma unroll
            for (int ms = 0; ms < 4; ms++) {
                uint32_t off = arow + (uint32_t)(ms * 16 * WROW);
                ldmx4(ahi[ms], sb + SM_WHI + off);
                ldmx4(alo[ms], sb + SM_WLO + off);
            }
            uint32_t brow = (uint32_t)((kk + (lane & 15)) * FROW +
                                       (wn * 32 + (lane >> 4) * 8) * 2);
#pragma unroll
            for (int np = 0; np < 2; np++) {
                uint32_t bhi[4], blo[4];
                uint32_t off = brow + (uint32_t)(np * 32);   // +16 cols * 2B
                ldmx4t(bhi, sb + SM_FHI + off);
                ldmx4t(blo, sb + SM_FLO + off);
#pragma unroll
                for (int ns = 0; ns < 2; ns++) {
                    int nidx = np * 2 + ns;
#pragma unroll
                    for (int ms = 0; ms < 4; ms++) {
                        mma_bf16(acc[ms][nidx], ahi[ms], bhi[2*ns], bhi[2*ns+1]);
                        mma_bf16(acc[ms][nidx], ahi[ms], blo[2*ns], blo[2*ns+1]);
                        mma_bf16(acc[ms][nidx], alo[ms], bhi[2*ns], bhi[2*ns+1]);
                    }
                }
            }
        }
    }

    // ---- stage acc (transpose): stage[spatial][channel] ----
    __syncthreads();
    float* stage = (float*)(smem + SM_STAGE);
#pragma unroll
    for (int ms = 0; ms < 4; ms++) {
        int mr = wm * 64 + ms * 16 + (lane >> 2);
#pragma unroll
        for (int nidx = 0; nidx < 4; nidx++) {
            int nc = wn * 32 + nidx * 8 + 2 * (lane & 3);
            stage[nc * STR + mr]           = acc[ms][nidx][0];
            stage[(nc + 1) * STR + mr]     = acc[ms][nidx][1];
            stage[nc * STR + mr + 8]       = acc[ms][nidx][2];
            stage[(nc + 1) * STR + mr + 8] = acc[ms][nidx][3];
        }
    }
    __syncthreads();

    // ---- decode: thread -> channel (uniform attr), 2 thread-halves x 64 rows
    const int cl = tid & 127;
    const int gh = tid >> 7;             // 0/1: spatial half
    const int c  = m0 + cl;
    if (c < 255) {
        const int a_   = c / 85;
        const int attr = c - a_ * 85;
        const float bm = ((const float*)(smem + SM_BIAS))[cl];
        float aw, ah;
        if (a_ == 0)      { aw = aw0; ah = ah0; }
        else if (a_ == 1) { aw = aw1; ah = ah1; }
        else              { aw = aw2; ah = ah2; }
        float* __restrict__ outb =
            out + ((size_t)b * 3 * HW + (size_t)a_ * HW) * 85;
#pragma unroll 4
        for (int r = 0; r < 64; r++) {
            int gl = gh * 64 + r;
            int g  = n0 + gl;
            if (g >= HW) break;
            float v = stage[gl * STR + cl] + bm;
            float res;
            if (attr == 0)      res = ((float)(g % S) + sigmoidf_(v)) * invS;
            else if (attr == 1) res = ((float)(g / S) + sigmoidf_(v)) * invS;
            else if (attr == 2) res = __expf(v) * aw;
            else if (attr == 3) res = __expf(v) * ah;
            else                res = sigmoidf_(v);
            outb[(size_t)g * 85 + attr] = res;
        }
    }
}

extern "C" void kernel_launch(void* const* d_in, const int* in_sizes, int n_in,
                              void* d_out, int out_size) {
    const float* f13 = (const float*)d_in[0];
    const float* f26 = (const float*)d_in[1];
    const float* f52 = (const float*)d_in[2];
    const float* W13 = (const float*)d_in[3];
    const float* b13 = (const float*)d_in[4];
    const float* W26 = (const float*)d_in[5];
    const float* b26 = (const float*)d_in[6];
    const float* W52 = (const float*)d_in[7];
    const float* b52 = (const float*)d_in[8];
    float* out = (float*)d_out;
    (void)in_sizes; (void)n_in; (void)out_size;

    // Idempotent, capture-safe; called every launch (no static state).
    cudaFuncSetAttribute(head_mma,
                         cudaFuncAttributeMaxDynamicSharedMemorySize,
                         SMEM_TOTAL);

    const int B = 32;
    const size_t off26 = (size_t)B * 3 * 169 * 85;
    const size_t off52 = off26 + (size_t)B * 3 * 676 * 85;

    prep_kernel<<<1024, 256>>>(W13, W26, W52);

    const float inv416 = 1.f / 416.f;

    // head13: K=1024, S=13, HW=169, anchors (116,90)(156,198)(373,326)
    {
        dim3 grid((169 + 127) / 128, 2, B);
        head_mma<<<grid, 256, SMEM_TOTAL>>>(f13, 0, b13, out,
                                            1024, 13, 169, 1.f / 13.f,
                                            116.f * inv416, 90.f * inv416,
                                            156.f * inv416, 198.f * inv416,
                                            373.f * inv416, 326.f * inv416);
    }
    // head26: K=512, S=26, HW=676, anchors (30,61)(62,45)(59,119)
    {
        dim3 grid((676 + 127) / 128, 2, B);
        head_mma<<<grid, 256, SMEM_TOTAL>>>(f26, 1, b26, out + off26,
                                            512, 26, 676, 1.f / 26.f,
                                            30.f * inv416, 61.f * inv416,
                                            62.f * inv416, 45.f * inv416,
                                            59.f * inv416, 119.f * inv416);
    }
    // head52: K=256, S=52, HW=2704, anchors (10,13)(16,30)(33,23)
    {
        dim3 grid((2704 + 127) / 128, 2, B);
        head_mma<<<grid, 256, SMEM_TOTAL>>>(f52, 2, b52, out + off52,
                                            256, 52, 2704, 1.f / 52.f,
                                            10.f * inv416, 13.f * inv416,
                                            16.f * inv416, 30.f * inv416,
                                            33.f * inv416, 23.f * inv416);
    }
}